// round 16
// baseline (speedup 1.0000x reference)
#include <cuda_runtime.h>
#include <cuda_fp16.h>
#include <cstdint>

#define BB 16
#define TT 96
#define TP1 97
#define HW 16384
#define NSTEP 6
#define MTHR 0.9f
#define NBLK 512            // co-resident (4+/SM guaranteed)
#define PXB 512             // pixels owned per block (both phases)
#define BPB 32              // blocks per batch

// ---- scratch (device globals; no allocation APIs) ----
__device__ __half        g_D[(size_t)BB * HW * TT]; // d[b][p][t] fp16, t contiguous (~50MB)
__device__ double        g_delta[BB * TP1];         // idx0 = empty template, always 0
__device__ unsigned char g_topcov[BB * HW];
__device__ float         g_topval[BB * HW];
__device__ int           g_bcnt[8];
__device__ int           g_bgen[8];                 // monotonic generations

// ---------------------------------------------------------------------------
// Grid-wide barrier — EXACT R12 version (RMW polling; proven correct).
__device__ __forceinline__ void grid_barrier(int slot) {
    __syncthreads();
    __threadfence();
    if (threadIdx.x == 0) {
        int g   = atomicAdd(&g_bgen[slot], 0);
        int old = atomicAdd(&g_bcnt[slot], 1);
        if (old == NBLK - 1) {
            g_bcnt[slot] = 0;
            __threadfence();
            atomicExch(&g_bgen[slot], g + 1);
        } else {
            while (atomicAdd(&g_bgen[slot], 0) == g) __nanosleep(64);
        }
    }
    __syncthreads();
    __threadfence();
}

// ---------------------------------------------------------------------------
__device__ __forceinline__ void cp16(unsigned int dst_smem, const void* src) {
    asm volatile("cp.async.cg.shared.global [%0], [%1], 16;"
                 :: "r"(dst_smem), "l"(src));
}
#define CP_COMMIT() asm volatile("cp.async.commit_group;" ::: "memory")
#define CP_WAIT1()  asm volatile("cp.async.wait_group 1;" ::: "memory")
#define CP_WAIT0()  asm volatile("cp.async.wait_group 0;" ::: "memory")

// ---------------------------------------------------------------------------
struct SmemPre {
    float xs[64]; float eb[64];
    float tbuf[2][16][64];   // 8KB: 16-template stage of temps (double-buffered)
    float mbuf[2][16][64];   // 8KB: masks
    float dsm[64][TP1];      // transpose buffer (stride 97)
};
struct SmemStep { int list[PXB]; float partial[2][TT]; unsigned wm[8]; int scid; };
union __align__(16) SmemU { SmemPre pre; SmemStep st; };

__global__ void __launch_bounds__(256, 5)
k_all(const float* __restrict__ x,
      const float* __restrict__ temps,
      const float* __restrict__ msks,
      const float* __restrict__ bg,
      float* __restrict__ out) {
    __shared__ SmemU sm;
    __shared__ float accd[TT];           // phase-A delta0 accumulator (R12 reduce)
    __shared__ unsigned char used[TP1];

    const int tid = threadIdx.x;
    const int blk = blockIdx.x;
    const int b   = blk >> 5;            // 32 blocks per batch
    const int jj  = blk & 31;
    const int p0g = jj * PXB;            // block's 512-pixel slice

    if (tid < TP1) used[tid] = 0;
    if (tid < TT)  accd[tid] = 0.f;

    // --- zero g_delta, visible before any publish ---
    if (blk < BB && tid < TP1) g_delta[blk * TP1 + tid] = 0.0;
    grid_barrier(7);

    // cp.async destination addresses (per-thread, fixed across stages/tiles)
    const int crow = tid >> 4;           // template-within-stage 0..15
    const int coff = tid & 15;           // 16B chunk within 256B row
    unsigned int tdst[2], mdst[2];
    tdst[0] = (unsigned int)__cvta_generic_to_shared(&sm.pre.tbuf[0][crow][coff * 4]);
    tdst[1] = (unsigned int)__cvta_generic_to_shared(&sm.pre.tbuf[1][crow][coff * 4]);
    mdst[0] = (unsigned int)__cvta_generic_to_shared(&sm.pre.mbuf[0][crow][coff * 4]);
    mdst[1] = (unsigned int)__cvta_generic_to_shared(&sm.pre.mbuf[1][crow][coff * 4]);

    // ============ Phase A: cp.async-pipelined precompute on own 8 tiles =====
    for (int ti = 0; ti < 8; ti++) {
        const int p0 = p0g + ti * 64;

        if (tid < 64) {
            float xv = x[b * HW + p0 + tid];
            float bv = bg[p0 + tid];
            sm.pre.xs[tid] = xv;
            float e = xv - bv;
            sm.pre.eb[tid] = e * e;
            g_topcov[b * HW + p0 + tid] = 0;
        }

        // issue stages 0 and 1
        {
            const size_t rbase = (size_t)(b * TT + crow) * HW + p0 + coff * 4;
            cp16(tdst[0], temps + rbase);
            cp16(mdst[0], msks  + rbase);
            CP_COMMIT();
            cp16(tdst[1], temps + rbase + (size_t)16 * HW);
            cp16(mdst[1], msks  + rbase + (size_t)16 * HW);
            CP_COMMIT();
        }

        #pragma unroll
        for (int s = 0; s < 6; s++) {
            if (s < 5) CP_WAIT1(); else CP_WAIT0();   // group s complete (per-thread)
            __syncthreads();                          // block-visible; prev compute done

            const int bf  = s & 1;
            const int tt  = tid >> 4;
            const int px4 = tid & 15;
            const int t   = s * 16 + tt;
            float4 tv = *(const float4*)&sm.pre.tbuf[bf][tt][px4 * 4];
            float4 mv = *(const float4*)&sm.pre.mbuf[bf][tt][px4 * 4];
            const int p = 4 * px4;
            float d0 = 0.f, d1 = 0.f, d2 = 0.f, d3 = 0.f;
            if (mv.x > MTHR) { float a = sm.pre.xs[p]     - tv.x * mv.x; d0 = a * a - sm.pre.eb[p];     }
            if (mv.y > MTHR) { float a = sm.pre.xs[p + 1] - tv.y * mv.y; d1 = a * a - sm.pre.eb[p + 1]; }
            if (mv.z > MTHR) { float a = sm.pre.xs[p + 2] - tv.z * mv.z; d2 = a * a - sm.pre.eb[p + 2]; }
            if (mv.w > MTHR) { float a = sm.pre.xs[p + 3] - tv.w * mv.w; d3 = a * a - sm.pre.eb[p + 3]; }
            sm.pre.dsm[p][t]     = d0;
            sm.pre.dsm[p + 1][t] = d1;
            sm.pre.dsm[p + 2][t] = d2;
            sm.pre.dsm[p + 3][t] = d3;

            __syncthreads();                          // compute(s) done block-wide
            if (s + 2 < 6) {                          // refill buffer (s&1)
                const size_t rbase = (size_t)(b * TT + (s + 2) * 16 + crow) * HW + p0 + coff * 4;
                cp16(tdst[bf], temps + rbase);
                cp16(mdst[bf], msks  + rbase);
                CP_COMMIT();
            }
        }

        // pack + store D as fp16, t-contiguous: 64*96 halves = 768 uint4
        {
            __half* dst = g_D + ((size_t)b * HW + p0) * TT;
            for (int i = tid; i < 768; i += 256) {
                int r = i / 12, c = (i % 12) * 8;
                __half2 h0 = __floats2half2_rn(sm.pre.dsm[r][c    ], sm.pre.dsm[r][c + 1]);
                __half2 h1 = __floats2half2_rn(sm.pre.dsm[r][c + 2], sm.pre.dsm[r][c + 3]);
                __half2 h2 = __floats2half2_rn(sm.pre.dsm[r][c + 4], sm.pre.dsm[r][c + 5]);
                __half2 h3 = __floats2half2_rn(sm.pre.dsm[r][c + 6], sm.pre.dsm[r][c + 7]);
                uint4 v = make_uint4(*(unsigned*)&h0, *(unsigned*)&h1,
                                     *(unsigned*)&h2, *(unsigned*)&h3);
                *(uint4*)(dst + (size_t)i * 8) = v;
            }
        }

        // delta0 from the SAME half-rounded values (exact R12 reduce)
        if (tid < TT) {
            float s = 0.f;
            #pragma unroll
            for (int p = 0; p < 64; p++)
                s += __half2float(__float2half_rn(sm.pre.dsm[p][tid]));
            accd[tid] += s;
        }
        __syncthreads();   // protect smem reuse next tile
    }
    if (tid < TT)
        atomicAdd(&g_delta[b * TP1 + 1 + tid], (double)accd[tid]);

    grid_barrier(0);

    // ============ Phase B: 6 greedy steps on own 512 pixels (R12 exact) =====
    for (int s = 0; s < NSTEP; s++) {
        if (tid < 32) {
            double bestv = 1e300;
            int    besti = TP1;
            for (int t = tid; t < TP1; t += 32) {
                double v = __ldcg(&g_delta[b * TP1 + t]);
                if (used[t]) v = 1e30;
                if (v < bestv) { bestv = v; besti = t; }   // earliest on tie
            }
            for (int off = 16; off; off >>= 1) {
                double ov = __shfl_down_sync(0xffffffffu, bestv, off);
                int    oi = __shfl_down_sync(0xffffffffu, besti, off);
                if (ov < bestv || (ov == bestv && oi < besti)) { bestv = ov; besti = oi; }
            }
            if (tid == 0) {
                sm.st.scid = besti;
                if (besti != 0) used[besti] = 1;
            }
        }
        __syncthreads();
        const int cid = sm.st.scid;

        int base = 0;
        if (cid != 0) {
            const size_t mrow = (size_t)(b * TT + cid - 1) * HW;
            #pragma unroll
            for (int k = 0; k < PXB / 256; k++) {
                int lp = k * 256 + tid;
                int p  = p0g + lp;
                int q  = b * HW + p;
                bool nw = false;
                float mv = msks[mrow + p];
                if (mv > MTHR && !g_topcov[q]) {
                    g_topval[q] = temps[mrow + p] * mv;  // goes UNDER existing
                    g_topcov[q] = 1;
                    nw = true;
                }
                unsigned m = __ballot_sync(0xffffffffu, nw);
                if ((tid & 31) == 0) sm.st.wm[tid >> 5] = m;
                __syncthreads();
                int off = base, tot = 0;
                #pragma unroll
                for (int w = 0; w < 8; w++) {
                    int c = __popc(sm.st.wm[w]);
                    if (w < (tid >> 5)) off += c;
                    tot += c;
                }
                if (nw) sm.st.list[off + __popc(m & ((1u << (tid & 31)) - 1))] = lp;
                base += tot;
                __syncthreads();
            }
        }
        const int n = base;

        if (s == NSTEP - 1) {
            #pragma unroll
            for (int k = 0; k < PXB / 256; k++) {
                int p = p0g + k * 256 + tid;
                int q = b * HW + p;
                out[q] = g_topcov[q] ? g_topval[q] : bg[p];
            }
        } else {
            if (n > 0) {
                const int grp = tid >> 7;
                const int lt  = tid & 127;
                float a0 = 0.f, a1 = 0.f, a2 = 0.f, a3 = 0.f;
                if (lt < TT) {
                    const __half* Db = g_D + ((size_t)b * HW + p0g) * TT + lt;
                    int j = grp;
                    for (; j + 6 < n; j += 8) {
                        a0 += __half2float(Db[(size_t)sm.st.list[j    ] * TT]);
                        a1 += __half2float(Db[(size_t)sm.st.list[j + 2] * TT]);
                        a2 += __half2float(Db[(size_t)sm.st.list[j + 4] * TT]);
                        a3 += __half2float(Db[(size_t)sm.st.list[j + 6] * TT]);
                    }
                    for (; j < n; j += 2) a0 += __half2float(Db[(size_t)sm.st.list[j] * TT]);
                    sm.st.partial[grp][lt] = (a0 + a1) + (a2 + a3);
                }
                __syncthreads();
                if (tid < TT) {
                    float tot2 = sm.st.partial[0][tid] + sm.st.partial[1][tid];
                    atomicAdd(&g_delta[b * TP1 + 1 + tid], -(double)tot2);
                }
            }
            grid_barrier(1 + s);
        }
    }
}

// ---------------------------------------------------------------------------
extern "C" void kernel_launch(void* const* d_in, const int* in_sizes, int n_in,
                              void* d_out, int out_size) {
    const float* x      = (const float*)d_in[0];   // (16,1,128,128)
    const float* temps  = (const float*)d_in[1];   // (16,96,1,128,128)
    const float* msks   = (const float*)d_in[2];   // (16,96,1,128,128)
    const float* bg     = (const float*)d_in[3];   // (1,128,128)
    float* out = (float*)d_out;                    // (16,1,128,128)

    k_all<<<NBLK, 256>>>(x, temps, msks, bg, out);
}

// round 17
// speedup vs baseline: 1.1864x; 1.1864x over previous
#include <cuda_runtime.h>
#include <cuda_fp16.h>
#include <cstdint>

#define BB 16
#define TT 96
#define TP1 97
#define HW 16384
#define NSTEP 6
#define MTHR 0.9f
#define NBLK 512            // 4 blocks/SM * 148 SMs = 592 >= 512 (co-resident)
#define PXB 512             // pixels owned per block (both phases)
#define BPB 32              // blocks per batch

// ---- scratch (device globals; no allocation APIs) ----
__device__ __half        g_D[(size_t)BB * HW * TT]; // d[b][p][t] fp16, t contiguous (~50MB)
__device__ double        g_delta[BB * TP1];         // idx0 = empty template, always 0
__device__ unsigned char g_topcov[BB * HW];
__device__ float         g_topval[BB * HW];
__device__ int           g_bcnt[8];
__device__ int           g_bgen[8];                 // monotonic generations

// ---------------------------------------------------------------------------
// Grid-wide barrier — EXACT R12 version (RMW polling; proven correct).
__device__ __forceinline__ void grid_barrier(int slot) {
    __syncthreads();
    __threadfence();
    if (threadIdx.x == 0) {
        int g   = atomicAdd(&g_bgen[slot], 0);
        int old = atomicAdd(&g_bcnt[slot], 1);
        if (old == NBLK - 1) {
            g_bcnt[slot] = 0;
            __threadfence();
            atomicExch(&g_bgen[slot], g + 1);
        } else {
            while (atomicAdd(&g_bgen[slot], 0) == g) __nanosleep(64);
        }
    }
    __syncthreads();
    __threadfence();
}

// ---------------------------------------------------------------------------
struct SmemPre { float xs[64]; float eb[64]; float dsm[64][TP1]; };
struct SmemStep { int list[PXB]; float partial[2][TT]; unsigned wm[8]; int scid; };
union SmemU { SmemPre pre; SmemStep st; };

__global__ void __launch_bounds__(256, 4)
k_all(const float* __restrict__ x,
      const float* __restrict__ temps,
      const float* __restrict__ msks,
      const float* __restrict__ bg,
      float* __restrict__ out) {
    __shared__ SmemU sm;
    __shared__ float accd[TT];           // phase-A delta0 accumulator (rounded values)
    __shared__ unsigned char used[TP1];

    const int tid = threadIdx.x;
    const int blk = blockIdx.x;
    const int b   = blk >> 5;            // 32 blocks per batch
    const int jj  = blk & 31;
    const int p0g = jj * PXB;            // block's 512-pixel slice

    if (tid < TP1) used[tid] = 0;
    if (tid < TT)  accd[tid] = 0.f;

    // --- zero g_delta, visible before any publish ---
    if (blk < BB && tid < TP1) g_delta[blk * TP1 + tid] = 0.0;
    grid_barrier(7);

    // ============ Phase A: precompute D (fp16) + delta0 on own 8 tiles ======
    const int ts  = tid >> 4;            // 16 templates per stage
    const int ps4 = tid & 15;            // float4 pixel group
    const int p   = 4 * ps4;

    for (int ti = 0; ti < 8; ti++) {
        const int p0 = p0g + ti * 64;

        if (tid < 64) {
            float xv = x[b * HW + p0 + tid];
            float bv = bg[p0 + tid];
            sm.pre.xs[tid] = xv;
            float e = xv - bv;
            sm.pre.eb[tid] = e * e;
            g_topcov[b * HW + p0 + tid] = 0;
        }
        __syncthreads();

        // two groups of 3 stages: ALL 6 float4 pairs loaded into registers
        // BEFORE any compute/STS -> forced >=6 outstanding LDG.128 per thread.
        #pragma unroll
        for (int gh = 0; gh < 2; gh++) {
            float4 tv[3], mv[3];
            #pragma unroll
            for (int k = 0; k < 3; k++) {
                int t = (gh * 3 + k) * 16 + ts;
                const size_t rb = (size_t)(b * TT + t) * HW + p0;
                tv[k] = __ldcs((const float4*)(temps + rb) + ps4);
                mv[k] = __ldcs((const float4*)(msks  + rb) + ps4);
            }
            #pragma unroll
            for (int k = 0; k < 3; k++) {
                int t = (gh * 3 + k) * 16 + ts;
                float d0 = 0.f, d1 = 0.f, d2 = 0.f, d3 = 0.f;
                if (mv[k].x > MTHR) { float a = sm.pre.xs[p]     - tv[k].x * mv[k].x; d0 = a * a - sm.pre.eb[p];     }
                if (mv[k].y > MTHR) { float a = sm.pre.xs[p + 1] - tv[k].y * mv[k].y; d1 = a * a - sm.pre.eb[p + 1]; }
                if (mv[k].z > MTHR) { float a = sm.pre.xs[p + 2] - tv[k].z * mv[k].z; d2 = a * a - sm.pre.eb[p + 2]; }
                if (mv[k].w > MTHR) { float a = sm.pre.xs[p + 3] - tv[k].w * mv[k].w; d3 = a * a - sm.pre.eb[p + 3]; }
                sm.pre.dsm[p][t]     = d0;
                sm.pre.dsm[p + 1][t] = d1;
                sm.pre.dsm[p + 2][t] = d2;
                sm.pre.dsm[p + 3][t] = d3;
            }
        }
        __syncthreads();

        // pack + store D as fp16, t-contiguous: 64*96 halves = 768 uint4
        {
            __half* dst = g_D + ((size_t)b * HW + p0) * TT;
            for (int i = tid; i < 768; i += 256) {
                int r = i / 12, c = (i % 12) * 8;
                __half2 h0 = __floats2half2_rn(sm.pre.dsm[r][c    ], sm.pre.dsm[r][c + 1]);
                __half2 h1 = __floats2half2_rn(sm.pre.dsm[r][c + 2], sm.pre.dsm[r][c + 3]);
                __half2 h2 = __floats2half2_rn(sm.pre.dsm[r][c + 4], sm.pre.dsm[r][c + 5]);
                __half2 h3 = __floats2half2_rn(sm.pre.dsm[r][c + 6], sm.pre.dsm[r][c + 7]);
                uint4 v = make_uint4(*(unsigned*)&h0, *(unsigned*)&h1,
                                     *(unsigned*)&h2, *(unsigned*)&h3);
                *(uint4*)(dst + (size_t)i * 8) = v;
            }
        }

        // delta0 from the SAME half-rounded values (exact incremental invariant)
        if (tid < TT) {
            float s = 0.f;
            #pragma unroll
            for (int pp = 0; pp < 64; pp++)
                s += __half2float(__float2half_rn(sm.pre.dsm[pp][tid]));
            accd[tid] += s;
        }
        __syncthreads();   // protect smem reuse next tile
    }
    if (tid < TT)
        atomicAdd(&g_delta[b * TP1 + 1 + tid], (double)accd[tid]);

    grid_barrier(0);

    // ============ Phase B: 6 greedy steps on own 512 pixels (R12 exact) =====
    for (int s = 0; s < NSTEP; s++) {
        if (tid < 32) {
            double bestv = 1e300;
            int    besti = TP1;
            for (int t = tid; t < TP1; t += 32) {
                double v = __ldcg(&g_delta[b * TP1 + t]);
                if (used[t]) v = 1e30;
                if (v < bestv) { bestv = v; besti = t; }   // earliest on tie
            }
            for (int off = 16; off; off >>= 1) {
                double ov = __shfl_down_sync(0xffffffffu, bestv, off);
                int    oi = __shfl_down_sync(0xffffffffu, besti, off);
                if (ov < bestv || (ov == bestv && oi < besti)) { bestv = ov; besti = oi; }
            }
            if (tid == 0) {
                sm.st.scid = besti;
                if (besti != 0) used[besti] = 1;
            }
        }
        __syncthreads();
        const int cid = sm.st.scid;

        int base = 0;
        if (cid != 0) {
            const size_t mrow = (size_t)(b * TT + cid - 1) * HW;
            #pragma unroll
            for (int k = 0; k < PXB / 256; k++) {
                int lp = k * 256 + tid;
                int pg = p0g + lp;
                int q  = b * HW + pg;
                bool nw = false;
                float mv = msks[mrow + pg];
                if (mv > MTHR && !g_topcov[q]) {
                    g_topval[q] = temps[mrow + pg] * mv;  // goes UNDER existing
                    g_topcov[q] = 1;
                    nw = true;
                }
                unsigned m = __ballot_sync(0xffffffffu, nw);
                if ((tid & 31) == 0) sm.st.wm[tid >> 5] = m;
                __syncthreads();
                int off = base, tot = 0;
                #pragma unroll
                for (int w = 0; w < 8; w++) {
                    int c = __popc(sm.st.wm[w]);
                    if (w < (tid >> 5)) off += c;
                    tot += c;
                }
                if (nw) sm.st.list[off + __popc(m & ((1u << (tid & 31)) - 1))] = lp;
                base += tot;
                __syncthreads();
            }
        }
        const int n = base;

        if (s == NSTEP - 1) {
            #pragma unroll
            for (int k = 0; k < PXB / 256; k++) {
                int pg = p0g + k * 256 + tid;
                int q  = b * HW + pg;
                out[q] = g_topcov[q] ? g_topval[q] : bg[pg];
            }
        } else {
            if (n > 0) {
                const int grp = tid >> 7;
                const int lt  = tid & 127;
                float a0 = 0.f, a1 = 0.f, a2 = 0.f, a3 = 0.f;
                if (lt < TT) {
                    const __half* Db = g_D + ((size_t)b * HW + p0g) * TT + lt;
                    int j = grp;
                    for (; j + 6 < n; j += 8) {
                        a0 += __half2float(Db[(size_t)sm.st.list[j    ] * TT]);
                        a1 += __half2float(Db[(size_t)sm.st.list[j + 2] * TT]);
                        a2 += __half2float(Db[(size_t)sm.st.list[j + 4] * TT]);
                        a3 += __half2float(Db[(size_t)sm.st.list[j + 6] * TT]);
                    }
                    for (; j < n; j += 2) a0 += __half2float(Db[(size_t)sm.st.list[j] * TT]);
                    sm.st.partial[grp][lt] = (a0 + a1) + (a2 + a3);
                }
                __syncthreads();
                if (tid < TT) {
                    float tot2 = sm.st.partial[0][tid] + sm.st.partial[1][tid];
                    atomicAdd(&g_delta[b * TP1 + 1 + tid], -(double)tot2);
                }
            }
            grid_barrier(1 + s);
        }
    }
}

// ---------------------------------------------------------------------------
extern "C" void kernel_launch(void* const* d_in, const int* in_sizes, int n_in,
                              void* d_out, int out_size) {
    const float* x      = (const float*)d_in[0];   // (16,1,128,128)
    const float* temps  = (const float*)d_in[1];   // (16,96,1,128,128)
    const float* msks   = (const float*)d_in[2];   // (16,96,1,128,128)
    const float* bg     = (const float*)d_in[3];   // (1,128,128)
    float* out = (float*)d_out;                    // (16,1,128,128)

    k_all<<<NBLK, 256>>>(x, temps, msks, bg, out);
}